// round 1
// baseline (speedup 1.0000x reference)
#include <cuda_runtime.h>
#include <cuda_fp16.h>
#include <cstdint>
#include <cstddef>

// Attention-modulated GRU scan. B=2048, T=200, D=U=128.
// Persistent CTAs: each CTA owns BT=16 batch rows for all 200 steps.
// Weights cached in smem as fp16 (padded for conflict-free ldmatrix).
// GEMMs via mma.sync.m16n8k16 (fp16 in, fp32 accum). h master state fp32 in smem.

#define TSTEPS   200
#define DDIM     128
#define UDIM     128
#define KDIM     256
#define BT       16
#define LDW      136   // weight row stride (halves): 128 + 8 pad -> conflict-free ldmatrix
#define LDA      264   // activation row stride (halves): 256 + 8 pad
#define LDH      132   // fp32 h row stride (floats): 128 + 4 pad
#define NTHREADS 256

#define OFF_W    0
#define SZ_W     (3 * 256 * LDW * 2)          // 208896
#define OFF_X    (OFF_W + SZ_W)               // 208896
#define SZ_X     (BT * LDA * 2)               // 8448
#define OFF_H    (OFF_X + SZ_X)               // 217344
#define SZ_H     (BT * LDH * 4)               // 8448
#define OFF_ATT  (OFF_H + SZ_H)               // 225792
#define OFF_B    (OFF_ATT + 64)               // 225856
#define SMEM_TOTAL (OFF_B + 3 * 128 * 4)      // 227392 bytes (< 227 KB limit)

__device__ __forceinline__ uint32_t smem_u32(const void* p) {
    uint32_t r;
    asm("{.reg .u64 t; cvta.to.shared.u64 t, %1; cvt.u32.u64 %0, t;}" : "=r"(r) : "l"(p));
    return r;
}

__device__ __forceinline__ void ldsm4(uint32_t addr, uint32_t& r0, uint32_t& r1, uint32_t& r2, uint32_t& r3) {
    asm volatile("ldmatrix.sync.aligned.m8n8.x4.shared.b16 {%0,%1,%2,%3}, [%4];"
                 : "=r"(r0), "=r"(r1), "=r"(r2), "=r"(r3) : "r"(addr));
}

__device__ __forceinline__ void ldsm4t(uint32_t addr, uint32_t& r0, uint32_t& r1, uint32_t& r2, uint32_t& r3) {
    asm volatile("ldmatrix.sync.aligned.m8n8.x4.trans.shared.b16 {%0,%1,%2,%3}, [%4];"
                 : "=r"(r0), "=r"(r1), "=r"(r2), "=r"(r3) : "r"(addr));
}

__device__ __forceinline__ void mma16816(float& c0, float& c1, float& c2, float& c3,
                                         uint32_t a0, uint32_t a1, uint32_t a2, uint32_t a3,
                                         uint32_t b0, uint32_t b1) {
    asm volatile("mma.sync.aligned.m16n8k16.row.col.f32.f16.f16.f32 "
                 "{%0,%1,%2,%3},{%4,%5,%6,%7},{%8,%9},{%0,%1,%2,%3};"
                 : "+f"(c0), "+f"(c1), "+f"(c2), "+f"(c3)
                 : "r"(a0), "r"(a1), "r"(a2), "r"(a3), "r"(b0), "r"(b1));
}

__device__ __forceinline__ float sigf(float x) { return 1.0f / (1.0f + __expf(-x)); }
__device__ __forceinline__ float tanhe(float x) {
    float e = __expf(-2.0f * x);
    return (1.0f - e) / (1.0f + e);
}

__global__ void __launch_bounds__(NTHREADS, 1)
gru_evolve_kernel(const float* __restrict__ X,   // (B,T,D)
                  const float* __restrict__ Att, // (B,T,1)
                  const float* __restrict__ Wu, const float* __restrict__ bu,
                  const float* __restrict__ Wr, const float* __restrict__ br,
                  const float* __restrict__ Wh, const float* __restrict__ bh,
                  float* __restrict__ Out)       // (B,U)
{
    extern __shared__ __align__(16) char smem[];
    __half* sW   = (__half*)(smem + OFF_W);   // [3][256][LDW]; gate 0=u,1=r,2=h
    __half* sX   = (__half*)(smem + OFF_X);   // [BT][LDA]; cols 0..127 = x, 128..255 = h (then r*h)
    float*  sH   = (float*)(smem + OFF_H);    // [BT][LDH] fp32 master h
    float*  sAtt = (float*)(smem + OFF_ATT);  // [BT]
    float*  sB   = (float*)(smem + OFF_B);    // bu | br | bh (128 each)

    const int tid = threadIdx.x;
    const int b0  = blockIdx.x * BT;

    // ---- one-time: weights -> fp16 smem. Wu/Wr rows permuted so A = [x | h]. Wh direct ([x | r*h]).
    for (int idx = tid; idx < 256 * 128; idx += NTHREADS) {
        int k = idx >> 7, n = idx & 127;
        int kp = (k + 128) & 255;
        sW[(0 * 256 + k) * LDW + n] = __float2half_rn(Wu[kp * UDIM + n]);
        sW[(1 * 256 + k) * LDW + n] = __float2half_rn(Wr[kp * UDIM + n]);
        sW[(2 * 256 + k) * LDW + n] = __float2half_rn(Wh[k * UDIM + n]);
    }
    if (tid < 128) { sB[tid] = bu[tid]; sB[128 + tid] = br[tid]; sB[256 + tid] = bh[tid]; }
    for (int idx = tid; idx < BT * LDH; idx += NTHREADS) sH[idx] = 0.0f;
    for (int idx = tid; idx < BT * 128; idx += NTHREADS) {
        int r = idx >> 7, c = idx & 127;
        sX[r * LDA + 128 + c] = __ushort_as_half((unsigned short)0);
    }

    // ---- per-thread x segment (16 threads per batch row, 8 floats each)
    const int xrow = tid >> 4;
    const int xseg = tid & 15;
    const float* xbase = X + ((size_t)(b0 + xrow) * TSTEPS) * DDIM + xseg * 8;
    float4 xa = *(const float4*)(xbase);
    float4 xb = *(const float4*)(xbase + 4);
    float attp = 0.0f;
    if (tid < BT) attp = Att[(size_t)(b0 + tid) * TSTEPS];

    // ---- fragment geometry
    const int lane = tid & 31;
    const int warp = tid >> 5;
    const int g = lane >> 2, q = lane & 3;
    const int nb = warp * 16;                 // warp owns output cols [nb, nb+16)

    const uint32_t sxaddr = smem_u32(sX);
    const uint32_t swaddr = smem_u32(sW);
    const uint32_t aLane = sxaddr + (uint32_t)(((lane & 15) * LDA + ((lane >> 4) << 3)) * 2);
    const uint32_t bLane = swaddr + (uint32_t)(((lane & 15) * LDW + nb + ((lane >> 4) << 3)) * 2);
    const uint32_t bUg = bLane;
    const uint32_t bRg = bLane + 256 * LDW * 2;
    const uint32_t bHg = bLane + 2 * 256 * LDW * 2;

    const int col0 = nb + 2 * q;
    const int col1 = nb + 8 + 2 * q;

    float hn0, hn1, hn2, hn3, hn4, hn5, hn6, hn7;

#pragma unroll 1
    for (int t = 0; t < TSTEPS; ++t) {
        // ---- write x(t) fp16 into sX[:,0:128] (prefetched); prefetch x(t+1)
        {
            __half2* dst = (__half2*)&sX[xrow * LDA + xseg * 8];
            dst[0] = __floats2half2_rn(xa.x, xa.y);
            dst[1] = __floats2half2_rn(xa.z, xa.w);
            dst[2] = __floats2half2_rn(xb.x, xb.y);
            dst[3] = __floats2half2_rn(xb.z, xb.w);
            if (tid < BT) sAtt[tid] = attp;
        }
        if (t + 1 < TSTEPS) {
            const float* xp = xbase + (size_t)(t + 1) * DDIM;
            xa = *(const float4*)xp;
            xb = *(const float4*)(xp + 4);
            if (tid < BT) attp = Att[(size_t)(b0 + tid) * TSTEPS + t + 1];
        }
        __syncthreads();  // A=[x|h] ready

        // ---- GEMM1: U_pre, R_pre = A @ Wu', A @ Wr'   (M=16, N=16/warp, K=256)
        float cU0 = 0, cU1 = 0, cU2 = 0, cU3 = 0, cU4 = 0, cU5 = 0, cU6 = 0, cU7 = 0;
        float cR0 = 0, cR1 = 0, cR2 = 0, cR3 = 0, cR4 = 0, cR5 = 0, cR6 = 0, cR7 = 0;
#pragma unroll
        for (int kk = 0; kk < KDIM; kk += 16) {
            uint32_t a0, a1, a2, a3, u0, u1, u2, u3, r0, r1, r2, r3;
            ldsm4(aLane + kk * 2, a0, a1, a2, a3);
            ldsm4t(bUg + kk * LDW * 2, u0, u1, u2, u3);
            ldsm4t(bRg + kk * LDW * 2, r0, r1, r2, r3);
            mma16816(cU0, cU1, cU2, cU3, a0, a1, a2, a3, u0, u1);
            mma16816(cU4, cU5, cU6, cU7, a0, a1, a2, a3, u2, u3);
            mma16816(cR0, cR1, cR2, cR3, a0, a1, a2, a3, r0, r1);
            mma16816(cR4, cR5, cR6, cR7, a0, a1, a2, a3, r2, r3);
        }
        __syncthreads();  // all warps done reading sX h-part -> safe to overwrite with r*h

        // ---- r = sigmoid(R_pre + br); write fp16(r*h) into sX[:,128:256]; keep h in regs
        float h0x, h0y, h1x, h1y, h2x, h2y, h3x, h3y;
        {
            float2 ht = *(float2*)&sH[g * LDH + col0];
            float2 hb = *(float2*)&sH[(g + 8) * LDH + col0];
            float bv0 = sB[128 + col0], bv1 = sB[128 + col0 + 1];
            float r00 = sigf(cR0 + bv0), r01 = sigf(cR1 + bv1);
            float r10 = sigf(cR2 + bv0), r11 = sigf(cR3 + bv1);
            *(__half2*)&sX[g * LDA + 128 + col0]       = __floats2half2_rn(r00 * ht.x, r01 * ht.y);
            *(__half2*)&sX[(g + 8) * LDA + 128 + col0] = __floats2half2_rn(r10 * hb.x, r11 * hb.y);
            h0x = ht.x; h0y = ht.y; h1x = hb.x; h1y = hb.y;
        }
        {
            float2 ht = *(float2*)&sH[g * LDH + col1];
            float2 hb = *(float2*)&sH[(g + 8) * LDH + col1];
            float bv0 = sB[128 + col1], bv1 = sB[128 + col1 + 1];
            float r00 = sigf(cR4 + bv0), r01 = sigf(cR5 + bv1);
            float r10 = sigf(cR6 + bv0), r11 = sigf(cR7 + bv1);
            *(__half2*)&sX[g * LDA + 128 + col1]       = __floats2half2_rn(r00 * ht.x, r01 * ht.y);
            *(__half2*)&sX[(g + 8) * LDA + 128 + col1] = __floats2half2_rn(r10 * hb.x, r11 * hb.y);
            h2x = ht.x; h2y = ht.y; h3x = hb.x; h3y = hb.y;
        }
        __syncthreads();  // A2=[x|r*h] ready

        // ---- GEMM2: H_pre = A2 @ Wh
        float cH0 = 0, cH1 = 0, cH2 = 0, cH3 = 0, cH4 = 0, cH5 = 0, cH6 = 0, cH7 = 0;
#pragma unroll
        for (int kk = 0; kk < KDIM; kk += 16) {
            uint32_t a0, a1, a2, a3, w0, w1, w2, w3;
            ldsm4(aLane + kk * 2, a0, a1, a2, a3);
            ldsm4t(bHg + kk * LDW * 2, w0, w1, w2, w3);
            mma16816(cH0, cH1, cH2, cH3, a0, a1, a2, a3, w0, w1);
            mma16816(cH4, cH5, cH6, cH7, a0, a1, a2, a3, w2, w3);
        }

        // ---- update: u = sigmoid(U_pre+bu)*a; hh = tanh(H_pre+bh); h' = u*hh + (1-u)*h
        {
            float at = sAtt[g], ab = sAtt[g + 8];
            {
                float bu0v = sB[col0], bu1v = sB[col0 + 1];
                float bh0v = sB[256 + col0], bh1v = sB[256 + col0 + 1];
                float u00 = sigf(cU0 + bu0v) * at, u01 = sigf(cU1 + bu1v) * at;
                float u10 = sigf(cU2 + bu0v) * ab, u11 = sigf(cU3 + bu1v) * ab;
                float t00 = tanhe(cH0 + bh0v), t01 = tanhe(cH1 + bh1v);
                float t10 = tanhe(cH2 + bh0v), t11 = tanhe(cH3 + bh1v);
                hn0 = u00 * t00 + (1.0f - u00) * h0x;
                hn1 = u01 * t01 + (1.0f - u01) * h0y;
                hn2 = u10 * t10 + (1.0f - u10) * h1x;
                hn3 = u11 * t11 + (1.0f - u11) * h1y;
                *(float2*)&sH[g * LDH + col0]       = make_float2(hn0, hn1);
                *(float2*)&sH[(g + 8) * LDH + col0] = make_float2(hn2, hn3);
            }
            {
                float bu0v = sB[col1], bu1v = sB[col1 + 1];
                float bh0v = sB[256 + col1], bh1v = sB[256 + col1 + 1];
                float u00 = sigf(cU4 + bu0v) * at, u01 = sigf(cU5 + bu1v) * at;
                float u10 = sigf(cU6 + bu0v) * ab, u11 = sigf(cU7 + bu1v) * ab;
                float t00 = tanhe(cH4 + bh0v), t01 = tanhe(cH5 + bh1v);
                float t10 = tanhe(cH6 + bh0v), t11 = tanhe(cH7 + bh1v);
                hn4 = u00 * t00 + (1.0f - u00) * h2x;
                hn5 = u01 * t01 + (1.0f - u01) * h2y;
                hn6 = u10 * t10 + (1.0f - u10) * h3x;
                hn7 = u11 * t11 + (1.0f - u11) * h3y;
                *(float2*)&sH[g * LDH + col1]       = make_float2(hn4, hn5);
                *(float2*)&sH[(g + 8) * LDH + col1] = make_float2(hn6, hn7);
            }
        }
        __syncthreads();  // all warps done with GEMM2 reads of sX h-part

        // ---- stage fp16(h') into sX h-part for next step's A
        *(__half2*)&sX[g * LDA + 128 + col0]       = __floats2half2_rn(hn0, hn1);
        *(__half2*)&sX[(g + 8) * LDA + 128 + col0] = __floats2half2_rn(hn2, hn3);
        *(__half2*)&sX[g * LDA + 128 + col1]       = __floats2half2_rn(hn4, hn5);
        *(__half2*)&sX[(g + 8) * LDA + 128 + col1] = __floats2half2_rn(hn6, hn7);
    }

    __syncthreads();
    for (int idx = tid; idx < BT * 128; idx += NTHREADS) {
        int r = idx >> 7, c = idx & 127;
        Out[(size_t)(b0 + r) * UDIM + c] = sH[r * LDH + c];
    }
}

extern "C" void kernel_launch(void* const* d_in, const int* in_sizes, int n_in,
                              void* d_out, int out_size) {
    const float* X   = (const float*)d_in[0];
    const float* Att = (const float*)d_in[1];
    const float* Wu  = (const float*)d_in[2];
    const float* bu  = (const float*)d_in[3];
    const float* Wr  = (const float*)d_in[4];
    const float* br  = (const float*)d_in[5];
    const float* Wh  = (const float*)d_in[6];
    const float* bh  = (const float*)d_in[7];
    float* Out = (float*)d_out;

    int B = in_sizes[0] / (TSTEPS * DDIM);   // 2048
    cudaFuncSetAttribute(gru_evolve_kernel,
                         cudaFuncAttributeMaxDynamicSharedMemorySize, SMEM_TOTAL);
    gru_evolve_kernel<<<B / BT, NTHREADS, SMEM_TOTAL>>>(X, Att, Wu, bu, Wr, br, Wh, bh, Out);
}

// round 6
// speedup vs baseline: 1.1643x; 1.1643x over previous
#include <cuda_runtime.h>
#include <cuda_fp16.h>
#include <cstdint>
#include <cstddef>

// Attention-modulated GRU scan. B=2048, T=200, D=U=128.
// R2: split-K restructure. Per step, only the h-dependent K=128 GEMMs are on the
// critical path; their weights live in REGISTERS (mma B-fragments loaded once).
// x-part GEMMs (K=128, step-independent) run as latency filler for step t+1.
// 2 barriers/step (was 4). h master state fp32 in registers (c-fragment layout).

#define TSTEPS   200
#define DDIM     128
#define UDIM     128
#define BT       16
#define LDW      136   // weight row stride (halves): conflict-free ldmatrix
#define LDA      136   // activation tile row stride (halves)
#define NTHREADS 256

#define OFF_W    0
#define SZ_W     (6 * 128 * LDW * 2)        // 208896: [ux|rx|hx|uh|rh|hh]
#define OFF_XB   (OFF_W + SZ_W)             // x double buffer: 2 x 16 x LDA halves
#define SZ_XB    (2 * BT * LDA * 2)         // 8704
#define OFF_HH   (OFF_XB + SZ_XB)           // fp16 h tile
#define OFF_RH   (OFF_HH + BT * LDA * 2)    // fp16 r*h tile
#define OFF_ATT  (OFF_RH + BT * LDA * 2)    // 2 x 16 floats
#define SMEM_TOTAL (OFF_ATT + 2 * 16 * 4)   // 226432 bytes

__device__ __forceinline__ uint32_t smem_u32(const void* p) {
    uint32_t r;
    asm("{.reg .u64 t; cvta.to.shared.u64 t, %1; cvt.u32.u64 %0, t;}" : "=r"(r) : "l"(p));
    return r;
}

__device__ __forceinline__ void ldsm4(uint32_t addr, uint32_t& r0, uint32_t& r1, uint32_t& r2, uint32_t& r3) {
    asm volatile("ldmatrix.sync.aligned.m8n8.x4.shared.b16 {%0,%1,%2,%3}, [%4];"
                 : "=r"(r0), "=r"(r1), "=r"(r2), "=r"(r3) : "r"(addr));
}

__device__ __forceinline__ void ldsm4t(uint32_t addr, uint32_t& r0, uint32_t& r1, uint32_t& r2, uint32_t& r3) {
    asm volatile("ldmatrix.sync.aligned.m8n8.x4.trans.shared.b16 {%0,%1,%2,%3}, [%4];"
                 : "=r"(r0), "=r"(r1), "=r"(r2), "=r"(r3) : "r"(addr));
}

__device__ __forceinline__ void mma16816(float& c0, float& c1, float& c2, float& c3,
                                         uint32_t a0, uint32_t a1, uint32_t a2, uint32_t a3,
                                         uint32_t b0, uint32_t b1) {
    asm volatile("mma.sync.aligned.m16n8k16.row.col.f32.f16.f16.f32 "
                 "{%0,%1,%2,%3},{%4,%5,%6,%7},{%8,%9},{%0,%1,%2,%3};"
                 : "+f"(c0), "+f"(c1), "+f"(c2), "+f"(c3)
                 : "r"(a0), "r"(a1), "r"(a2), "r"(a3), "r"(b0), "r"(b1));
}

__device__ __forceinline__ float sigf(float x) { return 1.0f / (1.0f + __expf(-x)); }
__device__ __forceinline__ float tanhe(float x) {
    float e = __expf(-2.0f * x);
    return (1.0f - e) / (1.0f + e);
}

__global__ void __launch_bounds__(NTHREADS, 1)
gru_evolve_kernel(const float* __restrict__ X,   // (B,T,D)
                  const float* __restrict__ Att, // (B,T,1)
                  const float* __restrict__ Wu, const float* __restrict__ bu,
                  const float* __restrict__ Wr, const float* __restrict__ br,
                  const float* __restrict__ Wh, const float* __restrict__ bh,
                  float* __restrict__ Out)       // (B,U)
{
    extern __shared__ __align__(16) char smem[];
    __half* sW   = (__half*)(smem + OFF_W);
    __half* sXB  = (__half*)(smem + OFF_XB);
    __half* sHH  = (__half*)(smem + OFF_HH);
    __half* sRH  = (__half*)(smem + OFF_RH);
    float*  sAtt = (float*)(smem + OFF_ATT);

    const int tid = threadIdx.x;
    const int b0  = blockIdx.x * BT;

    // ---- one-time weight staging (split at K=128):
    //  slot 0: Wu x-part (rows 128..255)   slot 3: Wu h-part (rows 0..127)
    //  slot 1: Wr x-part                   slot 4: Wr h-part
    //  slot 2: Wh x-part (rows 0..127)     slot 5: Wh rh-part (rows 128..255)
    for (int idx = tid; idx < 128 * 128; idx += NTHREADS) {
        int k = idx >> 7, n = idx & 127;
        sW[(0 * 128 + k) * LDW + n] = __float2half_rn(Wu[(128 + k) * UDIM + n]);
        sW[(1 * 128 + k) * LDW + n] = __float2half_rn(Wr[(128 + k) * UDIM + n]);
        sW[(2 * 128 + k) * LDW + n] = __float2half_rn(Wh[k * UDIM + n]);
        sW[(3 * 128 + k) * LDW + n] = __float2half_rn(Wu[k * UDIM + n]);
        sW[(4 * 128 + k) * LDW + n] = __float2half_rn(Wr[k * UDIM + n]);
        sW[(5 * 128 + k) * LDW + n] = __float2half_rn(Wh[(128 + k) * UDIM + n]);
    }
    // zero h tile
    for (int idx = tid; idx < BT * LDA; idx += NTHREADS)
        sHH[idx] = __ushort_as_half((unsigned short)0);

    // ---- x staging geometry: 16 threads per row, 8 floats each
    const int xrow = tid >> 4;
    const int xseg = tid & 15;
    const float* xbase = X + ((size_t)(b0 + xrow) * TSTEPS) * DDIM + xseg * 8;

    // stage x(0) into buffer parity 0
    {
        float4 a = *(const float4*)xbase;
        float4 b = *(const float4*)(xbase + 4);
        __half2* dst = (__half2*)&sXB[xrow * LDA + xseg * 8];
        dst[0] = __floats2half2_rn(a.x, a.y);
        dst[1] = __floats2half2_rn(a.z, a.w);
        dst[2] = __floats2half2_rn(b.x, b.y);
        dst[3] = __floats2half2_rn(b.z, b.w);
    }
    if (tid < BT) sAtt[tid] = Att[(size_t)(b0 + tid) * TSTEPS];

    // prefetch x(1), att(1)
    float4 xa = *(const float4*)(xbase + DDIM);
    float4 xb = *(const float4*)(xbase + DDIM + 4);
    float attA = (tid < BT) ? Att[(size_t)(b0 + tid) * TSTEPS + 1] : 0.0f;

    __syncthreads();

    // ---- fragment geometry
    const int lane = tid & 31;
    const int warp = tid >> 5;
    const int g = lane >> 2, q = lane & 3;
    const int nb = warp * 16;
    const int col0 = nb + 2 * q;
    const int col1 = nb + 8 + 2 * q;

    const uint32_t aOff  = (uint32_t)(((lane & 15) * LDA + ((lane >> 4) << 3)) * 2);
    const uint32_t aHH   = smem_u32(sHH) + aOff;
    const uint32_t aRH   = smem_u32(sRH) + aOff;
    const uint32_t aXB0  = smem_u32(sXB) + aOff;
    const uint32_t aXB1  = aXB0 + (uint32_t)(BT * LDA * 2);
    const uint32_t bLane = smem_u32(sW) +
        (uint32_t)(((lane & 15) * LDW + nb + ((lane >> 4) << 3)) * 2);

    // ---- biases -> regs
    const float bu0 = bu[col0], bu1 = bu[col0 + 1], bu2 = bu[col1], bu3 = bu[col1 + 1];
    const float br0 = br[col0], br1 = br[col0 + 1], br2 = br[col1], br3 = br[col1 + 1];
    const float bh0 = bh[col0], bh1 = bh[col0 + 1], bh2 = bh[col1], bh3 = bh[col1 + 1];

    // ---- recurrent-path weights -> registers (fragments, loaded once)
    uint32_t wU[32], wR[32], wH[32];
#pragma unroll
    for (int kk = 0; kk < 8; ++kk) {
        ldsm4t(bLane + (uint32_t)((3 * 128 + kk * 16) * LDW * 2), wU[4*kk], wU[4*kk+1], wU[4*kk+2], wU[4*kk+3]);
        ldsm4t(bLane + (uint32_t)((4 * 128 + kk * 16) * LDW * 2), wR[4*kk], wR[4*kk+1], wR[4*kk+2], wR[4*kk+3]);
        ldsm4t(bLane + (uint32_t)((5 * 128 + kk * 16) * LDW * 2), wH[4*kk], wH[4*kk+1], wH[4*kk+2], wH[4*kk+3]);
    }

    // ---- x-part GEMMs for t=0
    float xu[8], xr[8], xh[8];
#pragma unroll
    for (int i = 0; i < 8; ++i) { xu[i] = 0.f; xr[i] = 0.f; xh[i] = 0.f; }
#pragma unroll
    for (int kk = 0; kk < 8; ++kk) {
        uint32_t a0, a1, a2, a3, c0, c1, c2, c3;
        ldsm4(aXB0 + kk * 32, a0, a1, a2, a3);
        ldsm4t(bLane + (uint32_t)((0 * 128 + kk * 16) * LDW * 2), c0, c1, c2, c3);
        mma16816(xu[0], xu[1], xu[2], xu[3], a0, a1, a2, a3, c0, c1);
        mma16816(xu[4], xu[5], xu[6], xu[7], a0, a1, a2, a3, c2, c3);
        ldsm4t(bLane + (uint32_t)((1 * 128 + kk * 16) * LDW * 2), c0, c1, c2, c3);
        mma16816(xr[0], xr[1], xr[2], xr[3], a0, a1, a2, a3, c0, c1);
        mma16816(xr[4], xr[5], xr[6], xr[7], a0, a1, a2, a3, c2, c3);
        ldsm4t(bLane + (uint32_t)((2 * 128 + kk * 16) * LDW * 2), c0, c1, c2, c3);
        mma16816(xh[0], xh[1], xh[2], xh[3], a0, a1, a2, a3, c0, c1);
        mma16816(xh[4], xh[5], xh[6], xh[7], a0, a1, a2, a3, c2, c3);
    }

    float h[8];
#pragma unroll
    for (int i = 0; i < 8; ++i) h[i] = 0.f;

#pragma unroll 1
    for (int t = 0; t < TSTEPS; ++t) {
        // ---- GEMM1 (critical): xu += h @ Wuh ; xr += h @ Wrh   (B in regs)
#pragma unroll
        for (int kk = 0; kk < 8; ++kk) {
            uint32_t a0, a1, a2, a3;
            ldsm4(aHH + kk * 32, a0, a1, a2, a3);
            mma16816(xu[0], xu[1], xu[2], xu[3], a0, a1, a2, a3, wU[4*kk], wU[4*kk+1]);
            mma16816(xu[4], xu[5], xu[6], xu[7], a0, a1, a2, a3, wU[4*kk+2], wU[4*kk+3]);
            mma16816(xr[0], xr[1], xr[2], xr[3], a0, a1, a2, a3, wR[4*kk], wR[4*kk+1]);
            mma16816(xr[4], xr[5], xr[6], xr[7], a0, a1, a2, a3, wR[4*kk+2], wR[4*kk+3]);
        }

        // ---- gates: u = sig(.)*att, r = sig(.); write r*h tile
        const float at_ = sAtt[(t & 1) * 16 + g];
        const float ab_ = sAtt[(t & 1) * 16 + g + 8];
        float u0 = sigf(xu[0] + bu0) * at_, u1 = sigf(xu[1] + bu1) * at_;
        float u2 = sigf(xu[2] + bu0) * ab_, u3 = sigf(xu[3] + bu1) * ab_;
        float u4 = sigf(xu[4] + bu2) * at_, u5 = sigf(xu[5] + bu3) * at_;
        float u6 = sigf(xu[6] + bu2) * ab_, u7 = sigf(xu[7] + bu3) * ab_;
        {
            float r0 = sigf(xr[0] + br0), r1 = sigf(xr[1] + br1);
            float r2 = sigf(xr[2] + br0), r3 = sigf(xr[3] + br1);
            float r4 = sigf(xr[4] + br2), r5 = sigf(xr[5] + br3);
            float r6 = sigf(xr[6] + br2), r7 = sigf(xr[7] + br3);
            *(__half2*)&sRH[g * LDA + col0]       = __floats2half2_rn(r0 * h[0], r1 * h[1]);
            *(__half2*)&sRH[(g + 8) * LDA + col0] = __floats2half2_rn(r2 * h[2], r3 * h[3]);
            *(__half2*)&sRH[g * LDA + col1]       = __floats2half2_rn(r4 * h[4], r5 * h[5]);
            *(__half2*)&sRH[(g + 8) * LDA + col1] = __floats2half2_rn(r6 * h[6], r7 * h[7]);
        }

        // ---- stage x(t+1)/att(t+1) from regs; prefetch x(t+2)/att(t+2)
        if (t + 1 < TSTEPS) {
            __half2* dst = (__half2*)&sXB[((t + 1) & 1) * BT * LDA + xrow * LDA + xseg * 8];
            dst[0] = __floats2half2_rn(xa.x, xa.y);
            dst[1] = __floats2half2_rn(xa.z, xa.w);
            dst[2] = __floats2half2_rn(xb.x, xb.y);
            dst[3] = __floats2half2_rn(xb.z, xb.w);
            if (tid < BT) sAtt[((t + 1) & 1) * 16 + tid] = attA;
            if (t + 2 < TSTEPS) {
                const float* xp = xbase + (size_t)(t + 2) * DDIM;
                xa = *(const float4*)xp;
                xb = *(const float4*)(xp + 4);
                if (tid < BT) attA = Att[(size_t)(b0 + tid) * TSTEPS + t + 2];
            }
        }
        __syncthreads();   // barrier1: rh + x(t+1) ready; GEMM1 reads of sHH done

        // ---- GEMM2 (critical): xh += (r*h) @ Whh  (B in regs)
#pragma unroll
        for (int kk = 0; kk < 8; ++kk) {
            uint32_t a0, a1, a2, a3;
            ldsm4(aRH + kk * 32, a0, a1, a2, a3);
            mma16816(xh[0], xh[1], xh[2], xh[3], a0, a1, a2, a3, wH[4*kk], wH[4*kk+1]);
            mma16816(xh[4], xh[5], xh[6], xh[7], a0, a1, a2, a3, wH[4*kk+2], wH[4*kk+3]);
        }

        // ---- x-part GEMMs for t+1 (latency filler, independent of recurrence)
        float nxu[8], nxr[8], nxh[8];
#pragma unroll
        for (int i = 0; i < 8; ++i) { nxu[i] = 0.f; nxr[i] = 0.f; nxh[i] = 0.f; }
        if (t + 1 < TSTEPS) {
            const uint32_t aX = ((t + 1) & 1) ? aXB1 : aXB0;
#pragma unroll
            for (int kk = 0; kk < 8; ++kk) {
                uint32_t a0, a1, a2, a3, c0, c1, c2, c3;
                ldsm4(aX + kk * 32, a0, a1, a2, a3);
                ldsm4t(bLane + (uint32_t)((0 * 128 + kk * 16) * LDW * 2), c0, c1, c2, c3);
                mma16816(nxu[0], nxu[1], nxu[2], nxu[3], a0, a1, a2, a3, c0, c1);
                mma16816(nxu[4], nxu[5], nxu[6], nxu[7], a0, a1, a2, a3, c2, c3);
                ldsm4t(bLane + (uint32_t)((1 * 128 + kk * 16) * LDW * 2), c0, c1, c2, c3);
                mma16816(nxr[0], nxr[1], nxr[2], nxr[3], a0, a1, a2, a3, c0, c1);
                mma16816(nxr[4], nxr[5], nxr[6], nxr[7], a0, a1, a2, a3, c2, c3);
                ldsm4t(bLane + (uint32_t)((2 * 128 + kk * 16) * LDW * 2), c0, c1, c2, c3);
                mma16816(nxh[0], nxh[1], nxh[2], nxh[3], a0, a1, a2, a3, c0, c1);
                mma16816(nxh[4], nxh[5], nxh[6], nxh[7], a0, a1, a2, a3, c2, c3);
            }
        }

        // ---- h' = u*tanh(xh+bh) + (1-u)*h ; stage fp16(h') for next step
        {
            float t0 = tanhe(xh[0] + bh0), t1 = tanhe(xh[1] + bh1);
            float t2 = tanhe(xh[2] + bh0), t3 = tanhe(xh[3] + bh1);
            float t4 = tanhe(xh[4] + bh2), t5 = tanhe(xh[5] + bh3);
            float t6 = tanhe(xh[6] + bh2), t7 = tanhe(xh[7] + bh3);
            h[0] = u0 * t0 + (1.f - u0) * h[0];
            h[1] = u1 * t1 + (1.f - u1) * h[1];
            h[2] = u2 * t2 + (1.f - u2) * h[2];
            h[3] = u3 * t3 + (1.f - u3) * h[3];
            h[4] = u4 * t4 + (1.f - u4) * h[4];
            h[5] = u5 * t5 + (1.f - u5) * h[5];
            h[6] = u6 * t6 + (1.f - u6) * h[6];
            h[7] = u7 * t7 + (1.f - u7) * h[7];
            *(__half2*)&sHH[g * LDA + col0]       = __floats2half2_rn(h[0], h[1]);
            *(__half2*)&sHH[(g + 8) * LDA + col0] = __floats2half2_rn(h[2], h[3]);
            *(__half2*)&sHH[g * LDA + col1]       = __floats2half2_rn(h[4], h[5]);
            *(__half2*)&sHH[(g + 8) * LDA + col1] = __floats2half2_rn(h[6], h[7]);
        }
        __syncthreads();   // barrier2: h' tile ready; rh/x reads done

#pragma unroll
        for (int i = 0; i < 8; ++i) { xu[i] = nxu[i]; xr[i] = nxr[i]; xh[i] = nxh[i]; }
    }

    // ---- output from fp32 register state
    *(float2*)&Out[(size_t)(b0 + g) * UDIM + col0]     = make_float2(h[0], h[1]);
    *(float2*)&Out[(size_t)(b0 + g + 8) * UDIM + col0] = make_float2(h[2], h[3]);
    *(float2*)&Out[(size_t)(b0 + g) * UDIM + col1]     = make_float2(h[4], h[5]);
    *(float2*)&Out[(size_t)(b0 + g + 8) * UDIM + col1] = make_float2(h[6], h[7]);
}

extern "C" void kernel_launch(void* const* d_in, const int* in_sizes, int n_in,
                              void* d_out, int out_size) {
    const float* X   = (const float*)d_in[0];
    const float* Att = (const float*)d_in[1];
    const float* Wu  = (const float*)d_in[2];
    const float* bu  = (const float*)d_in[3];
    const float* Wr  = (const float*)d_in[4];
    const float* br  = (const float*)d_in[5];
    const float* Wh  = (const float*)d_in[6];
    const float* bh  = (const float*)d_in[7];
    float* Out = (float*)d_out;

    int B = in_sizes[0] / (TSTEPS * DDIM);   // 2048
    cudaFuncSetAttribute(gru_evolve_kernel,
                         cudaFuncAttributeMaxDynamicSharedMemorySize, SMEM_TOTAL);
    gru_evolve_kernel<<<B / BT, NTHREADS, SMEM_TOTAL>>>(X, Att, Wu, bu, Wr, br, Wh, bh, Out);
}